// round 5
// baseline (speedup 1.0000x reference)
#include <cuda_runtime.h>
#include <cuda_bf16.h>
#include <math.h>

#define NA 20000
#define PE 320000
#define FD 128
#define RD 64
#define DH 256
#define DG 192
#define KA 160      // a_* columns
#define KW1 224     // rbf(64) + a(160)
#define YW 512
#define NOACT (1<<30)

// dynamic smem layout for fused kernel (uints):
// As: [2][128][20] at 0      (5120)
// Bs: [2][128][20] at 5120   (5120)
// Hs: [8][128][20] at 10240  (20480)
#define SM_AS(b,r,c) sm[(b)*2560 + (r)*20 + (c)]
#define SM_BS(b,r,c) sm[5120 + (b)*2560 + (r)*20 + (c)]
#define SM_HS(s,r,c) sm[10240 + (s)*2560 + (r)*20 + (c)]
#define FUSED_SMEM ((10240+20480)*4)

// ---------------- scratch (device globals; no allocation allowed) ----------
__device__ float g_u [PE*3];
__device__ float g_X [(size_t)PE*KA];   // a_* only (block 1)
__device__ float g_GM[(size_t)PE*DG];   // [g0 0:32 | g1 32:64 | Mi 64:192]
__device__ float g_Y [(size_t)NA*YW];   // [Yi 0:256 | Yj 256:512]
__device__ float g_v0[NA*96];
__device__ float g_v1[NA*96];
__device__ float g_b1c[DH];
__device__ float g_tbuf[NA*FD];
__device__ __align__(16) unsigned short g_Bh[YW*FD > DH*KW1 ? YW*FD : DH*KW1];
__device__ __align__(16) unsigned short g_Bl[YW*FD > DH*KW1 ? YW*FD : DH*KW1];
__device__ __align__(16) unsigned short g_B2h[DG*FD];   // stage2: [eqW2 64 rows | invW2 128 rows]
__device__ __align__(16) unsigned short g_B2l[DG*FD];

__device__ __forceinline__ float silu_f(float x){ return x/(1.f+__expf(-x)); }

__device__ __forceinline__ void split1(float x, unsigned short &h, unsigned short &l){
    __nv_bfloat16 hb = __float2bfloat16(x);
    float r = x - __bfloat162float(hb);
    __nv_bfloat16 lb = __float2bfloat16(r);
    h = *reinterpret_cast<unsigned short*>(&hb);
    l = *reinterpret_cast<unsigned short*>(&lb);
}
__device__ __forceinline__ void split2(float x, float y, unsigned &h, unsigned &l){
    __nv_bfloat162 hb = __floats2bfloat162_rn(x, y);
    float rx = x - __bfloat162float(hb.x);
    float ry = y - __bfloat162float(hb.y);
    __nv_bfloat162 lb = __floats2bfloat162_rn(rx, ry);
    h = *reinterpret_cast<unsigned*>(&hb);
    l = *reinterpret_cast<unsigned*>(&lb);
}

__device__ __forceinline__ void mma_bf16(float* c, unsigned a0,unsigned a1,unsigned a2,unsigned a3,
                                         unsigned b0, unsigned b1){
    asm volatile("mma.sync.aligned.m16n8k16.row.col.f32.bf16.bf16.f32 "
        "{%0,%1,%2,%3}, {%4,%5,%6,%7}, {%8,%9}, {%0,%1,%2,%3};"
        : "+f"(c[0]), "+f"(c[1]), "+f"(c[2]), "+f"(c[3])
        : "r"(a0),"r"(a1),"r"(a2),"r"(a3),"r"(b0),"r"(b1));
}
__device__ __forceinline__ void ldsm_x4(unsigned &r0,unsigned &r1,unsigned &r2,unsigned &r3, const void* p){
    unsigned addr = (unsigned)__cvta_generic_to_shared(p);
    asm volatile("ldmatrix.sync.aligned.m8n8.x4.shared.b16 {%0,%1,%2,%3}, [%4];"
        : "=r"(r0),"=r"(r1),"=r"(r2),"=r"(r3) : "r"(addr));
}

// ---------------- small prep kernels ---------------------------------------
__global__ void prep_u_k(const float* __restrict__ vectors, const float* __restrict__ dist){
    int idx = blockIdx.x*blockDim.x + threadIdx.x;
    if(idx >= PE*3) return;
    g_u[idx] = vectors[idx] / (dist[idx/3] + 0.001f);
}

// Wy (K=128 -> N=512): node-side weights [W1i_eff | W1j_eff] with Wrbf folded.
__global__ void prep_wy_k(int b, const float* __restrict__ Wrbf,
                          const float* __restrict__ eqW1,
                          const float* __restrict__ invW1all){
    int idx = blockIdx.x*blockDim.x + threadIdx.x;
    if(idx >= YW*FD) return;
    int c = idx / FD, r = idx % FD;
    int sj = c >> 8;
    int cpack = c & 255;
    bool inv = (cpack >= FD);
    int cc = cpack & (FD-1);
    const float* W1 = inv ? (invW1all + (size_t)b*448*FD) : eqW1;
    int base;
    if(sj == 0) base = (inv || b==1) ? 192 : 32;
    else        base = (inv || b==1) ? 320 : 160;
    float val = W1[(base + r)*FD + cc];
    int wr = (sj ? 192 : 64) + r;
    #pragma unroll 8
    for(int k=0;k<32;k++) val += Wrbf[wr*32+k]*W1[k*FD+cc];
    unsigned short h,l; split1(val,h,l);
    g_Bh[(size_t)c*FD + r] = h;
    g_Bl[(size_t)c*FD + r] = l;
}

// W1 edge part (KW x 256)
__global__ void prep_w1split_k(int b, int KW, const float* __restrict__ Wrbf,
                          const float* __restrict__ eqW1, const float* __restrict__ eqb1,
                          const float* __restrict__ invW1all, const float* __restrict__ invb1all){
    int idx = blockIdx.x*blockDim.x + threadIdx.x;
    if(idx >= KW*DH) return;
    int r = idx / DH, c = idx % DH;
    bool inv = (c >= FD);
    int cc = c & (FD-1);
    const float* W1 = inv ? (invW1all + (size_t)b*448*FD) : eqW1;
    float acc = 0.f;
    if(r < 64){
        #pragma unroll 8
        for(int k=0;k<32;k++) acc += Wrbf[r*32+k]*W1[k*FD+cc];
    } else {
        int ar = r-64;
        if(inv || b==1) acc = W1[(32+ar)*FD+cc];
    }
    unsigned short h,l; split1(acc,h,l);
    g_Bh[(size_t)c*KW + r] = h;
    g_Bl[(size_t)c*KW + r] = l;
    if(r==0) g_b1c[c] = inv ? invb1all[b*FD+cc] : eqb1[cc];
}

// stage2 weights: rows 0:64 eqW2 (K=128), rows 64:192 invW2 (K=128); n-major
__global__ void prep_w2_k(int b, const float* __restrict__ eqW2,
                          const float* __restrict__ invW2all){
    int idx = blockIdx.x*blockDim.x + threadIdx.x;
    if(idx >= DG*FD) return;
    int c = idx / FD, r = idx % FD;
    float val;
    if(c < 64) val = eqW2[r*64 + c];
    else       val = invW2all[(size_t)b*FD*FD + r*FD + (c-64)];
    unsigned short h,l; split1(val,h,l);
    g_B2h[(size_t)c*FD + r] = h;
    g_B2l[(size_t)c*FD + r] = l;
}

// W1u = U1_top + Wemb @ U1_bot (128x128)
__global__ void prep_u1split_k(const float* __restrict__ U1, const float* __restrict__ Wemb){
    int idx = blockIdx.x*blockDim.x + threadIdx.x;
    if(idx >= FD*FD) return;
    int c = idx / FD, r = idx % FD;
    float val = U1[r*FD + c];
    #pragma unroll 8
    for(int k=0;k<FD;k++) val += Wemb[r*FD + k] * U1[(FD+k)*FD + c];
    unsigned short h,l; split1(val,h,l);
    g_Bh[(size_t)c*FD + r] = h;
    g_Bl[(size_t)c*FD + r] = l;
}
__global__ void prep_u2split_k(const float* __restrict__ U2){
    int idx = blockIdx.x*blockDim.x + threadIdx.x;
    if(idx >= FD*FD) return;
    int c = idx / FD, r = idx % FD;
    unsigned short h,l; split1(U2[r*FD + c],h,l);
    g_Bh[(size_t)c*FD + r] = h;
    g_Bl[(size_t)c*FD + r] = l;
}

// Per-edge a_* row (block 1 only)
__global__ void edge_x_k(const float* __restrict__ v_in,
                         const int* __restrict__ idx_i, const int* __restrict__ idx_j){
    int p = blockIdx.x*8 + threadIdx.y;
    int lane = threadIdx.x;
    int i = idx_i[p], j = idx_j[p];
    float* xr = g_X + (size_t)p*KA;
    float u0 = g_u[p*3+0], u1 = g_u[p*3+1], u2 = g_u[p*3+2];
    const float* vi  = v_in + (size_t)i*96;
    const float* vjp = v_in + (size_t)j*96;
    float vi0=vi[lane],  vi1=vi[32+lane],  vi2=vi[64+lane];
    float vj0=vjp[lane], vj1=vjp[32+lane], vj2=vjp[64+lane];
    xr[      lane] = u0*vi0 + u1*vi1 + u2*vi2;
    xr[ 32+lane] = u0*vj0 + u1*vj1 + u2*vj2;
    xr[ 64+lane] = vi0*vj0 + vi1*vj1 + vi2*vj2;
    xr[ 96+lane] = vi0*vi0 + vi1*vi1 + vi2*vi2;
    xr[128+lane] = vj0*vj0 + vj1*vj1 + vj2*vj2;
}

// ---------------- standalone bf16x3 GEMM (node-side) ------------------------
__global__ __launch_bounds__(256) void gemm_k(
    const float* __restrict__ A1, int lda1,
    const unsigned short* __restrict__ Bh, const unsigned short* __restrict__ Bl,
    const float* __restrict__ bias,
    float* __restrict__ C, int ldc,
    int M, int N, int K, int act_start, int accum)
{
    __shared__ unsigned As[2][128][20];
    __shared__ unsigned Bs[2][128][20];
    const int tid = threadIdx.x;
    const int lane = tid & 31, w = tid >> 5;
    const int wm = (w >> 2) * 64, wn = (w & 3) * 32;
    const int g = lane >> 2, tig = lane & 3;
    const int bm = blockIdx.y * 128, bn = blockIdx.x * 128;

    const int ar = tid >> 1;
    const int ak = (tid & 1) * 8;
    const int kc = ak >> 1;
    const int arow = bm + ar;
    const bool aok = arow < M;
    const bool bok = (bn + ar) < N;
    const unsigned short* Bhp = Bh + (size_t)(bn+ar)*K + ak;
    const unsigned short* Blp = Bl + (size_t)(bn+ar)*K + ak;

    float acc[4][4][4];
    #pragma unroll
    for(int i=0;i<4;i++)
        #pragma unroll
        for(int j=0;j<4;j++)
            #pragma unroll
            for(int q=0;q<4;q++) acc[i][j][q]=0.f;

    float4 a0v, a1v; uint4 bhv, blv;
    {
        const float* ap = A1 + (size_t)arow*lda1 + ak;
        a0v = aok ? *(const float4*)(ap)   : make_float4(0,0,0,0);
        a1v = aok ? *(const float4*)(ap+4) : make_float4(0,0,0,0);
    }
    bhv = bok ? *(const uint4*)(Bhp) : make_uint4(0,0,0,0);
    blv = bok ? *(const uint4*)(Blp) : make_uint4(0,0,0,0);

    const int nstage = K >> 4;
    for(int t=0; t<nstage; t++){
        const int cur = t & 1;
        {
            unsigned h0,l0,h1,l1,h2,l2,h3,l3;
            split2(a0v.x,a0v.y,h0,l0); split2(a0v.z,a0v.w,h1,l1);
            split2(a1v.x,a1v.y,h2,l2); split2(a1v.z,a1v.w,h3,l3);
            *(uint4*)&As[cur][ar][kc]   = make_uint4(h0,h1,h2,h3);
            *(uint4*)&As[cur][ar][8+kc] = make_uint4(l0,l1,l2,l3);
            *(uint4*)&Bs[cur][ar][kc]   = bhv;
            *(uint4*)&Bs[cur][ar][8+kc] = blv;
        }
        __syncthreads();
        if(t+1 < nstage){
            const int kk = (t+1)*16 + ak;
            const float* ap = A1 + (size_t)arow*lda1 + kk;
            a0v = aok ? *(const float4*)(ap)   : make_float4(0,0,0,0);
            a1v = aok ? *(const float4*)(ap+4) : make_float4(0,0,0,0);
            bhv = bok ? *(const uint4*)(Bhp + (t+1)*16) : make_uint4(0,0,0,0);
            blv = bok ? *(const uint4*)(Blp + (t+1)*16) : make_uint4(0,0,0,0);
        }
        unsigned bf[4][4];
        #pragma unroll
        for(int nt=0;nt<4;nt++){
            const unsigned* bp = &Bs[cur][wn + nt*8 + g][0];
            bf[nt][0]=bp[tig];   bf[nt][1]=bp[tig+4];
            bf[nt][2]=bp[8+tig]; bf[nt][3]=bp[8+tig+4];
        }
        #pragma unroll
        for(int mt=0;mt<4;mt++){
            unsigned ah0,ah1,ah2,ah3, al0,al1,al2,al3;
            const int row = wm + mt*16 + (lane & 15);
            const int kq  = (lane >> 4) * 4;
            ldsm_x4(ah0,ah1,ah2,ah3, &As[cur][row][kq]);
            ldsm_x4(al0,al1,al2,al3, &As[cur][row][8+kq]);
            #pragma unroll
            for(int nt=0;nt<4;nt++){
                mma_bf16(acc[mt][nt], ah0,ah1,ah2,ah3, bf[nt][0], bf[nt][1]);
                mma_bf16(acc[mt][nt], al0,al1,al2,al3, bf[nt][0], bf[nt][1]);
                mma_bf16(acc[mt][nt], ah0,ah1,ah2,ah3, bf[nt][2], bf[nt][3]);
            }
        }
        __syncthreads();
    }

    #pragma unroll
    for(int mt=0;mt<4;mt++){
        const int r0 = bm + wm + mt*16 + g;
        const bool r0ok = r0 < M, r1ok = (r0+8) < M;
        #pragma unroll
        for(int nt=0;nt<4;nt++){
            const int c0 = bn + wn + nt*8 + 2*tig;
            if(c0 >= N) continue;
            float x0=acc[mt][nt][0], x1=acc[mt][nt][1], x2=acc[mt][nt][2], x3=acc[mt][nt][3];
            if(c0 >= act_start){
                float bb0 = bias[c0], bb1 = bias[c0+1];
                x0 = silu_f(x0+bb0); x1 = silu_f(x1+bb1);
                x2 = silu_f(x2+bb0); x3 = silu_f(x3+bb1);
            }
            if(r0ok){
                float2* o = (float2*)&C[(size_t)r0*ldc + c0];
                if(accum){ float2 p=*o; *o = make_float2(p.x+x0, p.y+x1); }
                else      *o = make_float2(x0, x1);
            }
            if(r1ok){
                float2* o = (float2*)&C[(size_t)(r0+8)*ldc + c0];
                if(accum){ float2 p=*o; *o = make_float2(p.x+x2, p.y+x3); }
                else      *o = make_float2(x2, x3);
            }
        }
    }
}

// ---------------- fused edge kernel: H (smem) -> G/Mi ----------------------
// blockIdx.x==0: eq half  (stage1 cols 0:128,  stage2 eqW2 -> GM cols 0:64, raw)
// blockIdx.x==1: inv half (stage1 cols 128:256, stage2 invW2 -> GM cols 64:192, silu+bias)
__global__ __launch_bounds__(256) void fused_edge_k(
    const float* __restrict__ A1, int K1,          // rbfs, K1=64
    const float* __restrict__ A2, int lda2,        // g_X (block1) or unused
    const unsigned short* __restrict__ Bh, const unsigned short* __restrict__ Bl,
    const float* __restrict__ bias1,
    const float* __restrict__ Yg, const int* __restrict__ gi, const int* __restrict__ gj,
    const unsigned short* __restrict__ B2h, const unsigned short* __restrict__ B2l,
    const float* __restrict__ bias2,
    float* __restrict__ C, int K)
{
    extern __shared__ unsigned sm[];
    const int tid = threadIdx.x;
    const int lane = tid & 31, w = tid >> 5;
    const int wm = (w >> 2) * 64, wn = (w & 3) * 32;
    const int g = lane >> 2, tig = lane & 3;
    const int bx = blockIdx.x;
    const int bm = blockIdx.y * 128, bn = bx * 128;

    const int ar = tid >> 1;
    const int ak = (tid & 1) * 8;
    const int kc = ak >> 1;
    const int arow = bm + ar;
    const unsigned short* Bhp = Bh + (size_t)(bn+ar)*K + ak;
    const unsigned short* Blp = Bl + (size_t)(bn+ar)*K + ak;

    float acc[4][4][4];
    #pragma unroll
    for(int i=0;i<4;i++)
        #pragma unroll
        for(int j=0;j<4;j++)
            #pragma unroll
            for(int q=0;q<4;q++) acc[i][j][q]=0.f;

    float4 a0v, a1v; uint4 bhv, blv;
    {
        const float* ap = (ak < K1) ? A1 + (size_t)arow*K1 + ak
                                    : A2 + (size_t)arow*lda2 + (ak - K1);
        a0v = *(const float4*)(ap);
        a1v = *(const float4*)(ap+4);
    }
    bhv = *(const uint4*)(Bhp);
    blv = *(const uint4*)(Blp);

    const int nstage = K >> 4;
    for(int t=0; t<nstage; t++){
        const int cur = t & 1;
        {
            unsigned h0,l0,h1,l1,h2,l2,h3,l3;
            split2(a0v.x,a0v.y,h0,l0); split2(a0v.z,a0v.w,h1,l1);
            split2(a1v.x,a1v.y,h2,l2); split2(a1v.z,a1v.w,h3,l3);
            *(uint4*)&SM_AS(cur,ar,kc)   = make_uint4(h0,h1,h2,h3);
            *(uint4*)&SM_AS(cur,ar,8+kc) = make_uint4(l0,l1,l2,l3);
            *(uint4*)&SM_BS(cur,ar,kc)   = bhv;
            *(uint4*)&SM_BS(cur,ar,8+kc) = blv;
        }
        __syncthreads();
        if(t+1 < nstage){
            const int kk = (t+1)*16 + ak;
            const float* ap = (kk < K1) ? A1 + (size_t)arow*K1 + kk
                                        : A2 + (size_t)arow*lda2 + (kk - K1);
            a0v = *(const float4*)(ap);
            a1v = *(const float4*)(ap+4);
            bhv = *(const uint4*)(Bhp + (t+1)*16);
            blv = *(const uint4*)(Blp + (t+1)*16);
        }
        unsigned bf[4][4];
        #pragma unroll
        for(int nt=0;nt<4;nt++){
            const unsigned* bp = &SM_BS(cur, wn + nt*8 + g, 0);
            bf[nt][0]=bp[tig];   bf[nt][1]=bp[tig+4];
            bf[nt][2]=bp[8+tig]; bf[nt][3]=bp[8+tig+4];
        }
        #pragma unroll
        for(int mt=0;mt<4;mt++){
            unsigned ah0,ah1,ah2,ah3, al0,al1,al2,al3;
            const int row = wm + mt*16 + (lane & 15);
            const int kq  = (lane >> 4) * 4;
            ldsm_x4(ah0,ah1,ah2,ah3, &SM_AS(cur,row,kq));
            ldsm_x4(al0,al1,al2,al3, &SM_AS(cur,row,8+kq));
            #pragma unroll
            for(int nt=0;nt<4;nt++){
                mma_bf16(acc[mt][nt], ah0,ah1,ah2,ah3, bf[nt][0], bf[nt][1]);
                mma_bf16(acc[mt][nt], al0,al1,al2,al3, bf[nt][0], bf[nt][1]);
                mma_bf16(acc[mt][nt], ah0,ah1,ah2,ah3, bf[nt][2], bf[nt][3]);
            }
        }
        __syncthreads();
    }

    // ---- stage1 epilogue: bias + Y gather + silu -> Hs (split bf16) ----
    #pragma unroll
    for(int mt=0;mt<4;mt++){
        const int rl0 = wm + mt*16 + g;       // local rows rl0, rl0+8
        const int r0 = bm + rl0;
        const int i0=gi[r0],   j0=gj[r0];
        const int i1=gi[r0+8], j1=gj[r0+8];
        #pragma unroll
        for(int nt=0;nt<4;nt++){
            const int c0l = wn + nt*8 + 2*tig;    // local col 0..127
            const int c0g = bn + c0l;
            float x0=acc[mt][nt][0], x1=acc[mt][nt][1], x2=acc[mt][nt][2], x3=acc[mt][nt][3];
            {
                float2 yi = *(const float2*)&Yg[(size_t)i0*YW + c0g];
                float2 yj = *(const float2*)&Yg[(size_t)j0*YW + 256 + c0g];
                x0 += yi.x + yj.x; x1 += yi.y + yj.y;
                float2 yi1 = *(const float2*)&Yg[(size_t)i1*YW + c0g];
                float2 yj1 = *(const float2*)&Yg[(size_t)j1*YW + 256 + c0g];
                x2 += yi1.x + yj1.x; x3 += yi1.y + yj1.y;
            }
            float bb0 = bias1[c0g], bb1 = bias1[c0g+1];
            x0 = silu_f(x0+bb0); x1 = silu_f(x1+bb1);
            x2 = silu_f(x2+bb0); x3 = silu_f(x3+bb1);
            const int st = c0l >> 4;
            const int pi = (c0l & 15) >> 1;
            unsigned h,l;
            split2(x0,x1,h,l);
            SM_HS(st,rl0,pi) = h;  SM_HS(st,rl0,8+pi) = l;
            split2(x2,x3,h,l);
            SM_HS(st,rl0+8,pi) = h; SM_HS(st,rl0+8,8+pi) = l;
        }
    }
    __syncthreads();

    // ---- stage2: [128x128 H] @ W2 (K=128) -> G or Mi ----
    const int N2      = bx ? 128 : 64;
    const int outbase = bx ? 64 : 0;
    const bool b2ok = ar < N2;
    const unsigned short* B2hp = B2h + (size_t)(outbase+ar)*FD + ak;
    const unsigned short* B2lp = B2l + (size_t)(outbase+ar)*FD + ak;

    #pragma unroll
    for(int i=0;i<4;i++)
        #pragma unroll
        for(int j=0;j<4;j++)
            #pragma unroll
            for(int q=0;q<4;q++) acc[i][j][q]=0.f;

    bhv = b2ok ? *(const uint4*)(B2hp) : make_uint4(0,0,0,0);
    blv = b2ok ? *(const uint4*)(B2lp) : make_uint4(0,0,0,0);

    #pragma unroll
    for(int t=0; t<8; t++){
        const int cur = t & 1;
        *(uint4*)&SM_BS(cur,ar,kc)   = bhv;
        *(uint4*)&SM_BS(cur,ar,8+kc) = blv;
        __syncthreads();
        if(t+1 < 8){
            bhv = b2ok ? *(const uint4*)(B2hp + (t+1)*16) : make_uint4(0,0,0,0);
            blv = b2ok ? *(const uint4*)(B2lp + (t+1)*16) : make_uint4(0,0,0,0);
        }
        if(wn < N2){
            unsigned bf[4][4];
            #pragma unroll
            for(int nt=0;nt<4;nt++){
                const unsigned* bp = &SM_BS(cur, wn + nt*8 + g, 0);
                bf[nt][0]=bp[tig];   bf[nt][1]=bp[tig+4];
                bf[nt][2]=bp[8+tig]; bf[nt][3]=bp[8+tig+4];
            }
            #pragma unroll
            for(int mt=0;mt<4;mt++){
                unsigned ah0,ah1,ah2,ah3, al0,al1,al2,al3;
                const int row = wm + mt*16 + (lane & 15);
                const int kq  = (lane >> 4) * 4;
                ldsm_x4(ah0,ah1,ah2,ah3, &SM_HS(t,row,kq));
                ldsm_x4(al0,al1,al2,al3, &SM_HS(t,row,8+kq));
                #pragma unroll
                for(int nt=0;nt<4;nt++){
                    mma_bf16(acc[mt][nt], ah0,ah1,ah2,ah3, bf[nt][0], bf[nt][1]);
                    mma_bf16(acc[mt][nt], al0,al1,al2,al3, bf[nt][0], bf[nt][1]);
                    mma_bf16(acc[mt][nt], ah0,ah1,ah2,ah3, bf[nt][2], bf[nt][3]);
                }
            }
        }
        __syncthreads();
    }

    // ---- stage2 epilogue -> g_GM ----
    if(wn < N2){
        #pragma unroll
        for(int mt=0;mt<4;mt++){
            const int r0 = bm + wm + mt*16 + g;
            #pragma unroll
            for(int nt=0;nt<4;nt++){
                const int c0l = wn + nt*8 + 2*tig;
                if(c0l >= N2) continue;
                float x0=acc[mt][nt][0], x1=acc[mt][nt][1], x2=acc[mt][nt][2], x3=acc[mt][nt][3];
                if(bx){
                    float bb0 = bias2[c0l], bb1 = bias2[c0l+1];
                    x0 = silu_f(x0+bb0); x1 = silu_f(x1+bb1);
                    x2 = silu_f(x2+bb0); x3 = silu_f(x3+bb1);
                }
                *(float2*)&C[(size_t)r0*DG + outbase + c0l]     = make_float2(x0,x1);
                *(float2*)&C[(size_t)(r0+8)*DG + outbase + c0l] = make_float2(x2,x3);
            }
        }
    }
}

// ---------------- segment-sum scatters (idx_i sorted) -----------------------
__global__ void m_scatter_k(float* __restrict__ s_out,
                            const int* __restrict__ idx_i,
                            const float* __restrict__ cutoffs){
    int f  = threadIdx.x;
    int p0 = blockIdx.x*128;
    float acc = 0.f; int cur = idx_i[p0];
    for(int e=0;e<128;e++){
        int p = p0+e;
        int ii = idx_i[p];
        if(ii != cur){ atomicAdd(&s_out[(size_t)cur*FD+f], acc); acc = 0.f; cur = ii; }
        acc += g_GM[(size_t)p*DG + 64 + f] * cutoffs[p];
    }
    atomicAdd(&s_out[(size_t)cur*FD+f], acc);
}

__global__ void dv_scatter_k(const float* __restrict__ v_in, float* __restrict__ v_out,
                             const int* __restrict__ idx_i, const int* __restrict__ idx_j,
                             const float* __restrict__ cutoffs){
    int t = threadIdx.x;
    int m = t & 31, d = t >> 5;
    int p0 = blockIdx.x*128;
    float acc = 0.f; int cur = idx_i[p0];
    for(int e=0;e<128;e++){
        int p = p0+e;
        int ii = idx_i[p];
        if(ii != cur){ atomicAdd(&v_out[(size_t)cur*96+t], acc); acc = 0.f; cur = ii; }
        int j = idx_j[p];
        float g0 = g_GM[(size_t)p*DG + m];
        float g1 = g_GM[(size_t)p*DG + 32 + m];
        float vj = v_in[(size_t)j*96 + t];
        acc += (g0*g_u[p*3+d] + g1*vj) * cutoffs[p];
    }
    atomicAdd(&v_out[(size_t)cur*96+t], acc);
}

// ---------------- launch ----------------------------------------------------
extern "C" void kernel_launch(void* const* d_in, const int* in_sizes, int n_in,
                              void* d_out, int out_size)
{
    const float* features = (const float*)d_in[0];
    const float* distances= (const float*)d_in[1];
    const float* vectors  = (const float*)d_in[2];
    const float* cutoffs  = (const float*)d_in[3];
    const float* rbfs     = (const float*)d_in[4];
    const int*   idx_i    = (const int*)  d_in[5];
    const int*   idx_j    = (const int*)  d_in[6];
    const float* Wrbf     = (const float*)d_in[7];
    const float* Wemb     = (const float*)d_in[8];
    const float* eq0_W1   = (const float*)d_in[9];
    const float* eq0_b1   = (const float*)d_in[10];
    const float* eq0_W2   = (const float*)d_in[11];
    const float* eq1_W1   = (const float*)d_in[12];
    const float* eq1_b1   = (const float*)d_in[13];
    const float* eq1_W2   = (const float*)d_in[14];
    const float* inv_W1   = (const float*)d_in[15];
    const float* inv_b1   = (const float*)d_in[16];
    const float* inv_W2   = (const float*)d_in[17];
    const float* inv_b2   = (const float*)d_in[18];
    const float* upd_W1   = (const float*)d_in[19];
    const float* upd_b1   = (const float*)d_in[20];
    const float* upd_W2   = (const float*)d_in[21];
    const float* upd_b2   = (const float*)d_in[22];

    float* out_s = (float*)d_out;
    float* out_v = out_s + (size_t)NA*FD;

    float *pX,*pGM,*pY,*pv0,*pv1,*pb1,*pt;
    unsigned short *pBh,*pBl,*pB2h,*pB2l;
    cudaGetSymbolAddress((void**)&pX,  g_X);
    cudaGetSymbolAddress((void**)&pGM, g_GM);
    cudaGetSymbolAddress((void**)&pY,  g_Y);
    cudaGetSymbolAddress((void**)&pv0, g_v0);
    cudaGetSymbolAddress((void**)&pv1, g_v1);
    cudaGetSymbolAddress((void**)&pb1, g_b1c);
    cudaGetSymbolAddress((void**)&pt,  g_tbuf);
    cudaGetSymbolAddress((void**)&pBh, g_Bh);
    cudaGetSymbolAddress((void**)&pBl, g_Bl);
    cudaGetSymbolAddress((void**)&pB2h, g_B2h);
    cudaGetSymbolAddress((void**)&pB2l, g_B2l);

    cudaFuncSetAttribute(fused_edge_k, cudaFuncAttributeMaxDynamicSharedMemorySize, FUSED_SMEM);

    cudaMemcpyAsync(out_s, features, (size_t)NA*FD*sizeof(float), cudaMemcpyDeviceToDevice, 0);
    cudaMemsetAsync(pv0, 0, (size_t)NA*96*sizeof(float), 0);
    prep_u_k<<<(PE*3+255)/256, 256>>>(vectors, distances);

    const int MT = (NA+127)/128;

    for(int b=0;b<2;b++){
        const float* eqW1 = b ? eq1_W1 : eq0_W1;
        const float* eqb1 = b ? eq1_b1 : eq0_b1;
        const float* eqW2 = b ? eq1_W2 : eq0_W2;
        float* v_in  = b ? pv1  : pv0;
        float* v_out = b ? out_v: pv1;
        const int KW = b ? KW1 : 64;

        // Y = s @ [W1i_eff | W1j_eff]   (NA,128)@(128,512)
        prep_wy_k<<<(YW*FD+255)/256, 256>>>(b, Wrbf, eqW1, inv_W1);
        { dim3 g(4, MT);
          gemm_k<<<g,256>>>(out_s, FD, pBh, pBl, nullptr, pY, YW, NA, YW, FD, NOACT, 0); }

        prep_w1split_k<<<(KW*DH+255)/256, 256>>>(b, KW, Wrbf, eqW1, eqb1, inv_W1, inv_b1);
        prep_w2_k<<<(DG*FD+255)/256, 256>>>(b, eqW2, inv_W2);
        if(b) edge_x_k<<<PE/8, dim3(32,8)>>>(v_in, idx_i, idx_j);

        // fused: H (smem) -> [G | Mi] in g_GM
        { dim3 g(2, PE/128);
          fused_edge_k<<<g,256,FUSED_SMEM>>>(rbfs, RD, pX, KA, pBh, pBl, pb1,
                                             pY, idx_i, idx_j,
                                             pB2h, pB2l, inv_b2 + b*FD, pGM, KW); }

        // v_out = v_in + segment_sum(dv)
        cudaMemcpyAsync(v_out, v_in, (size_t)NA*96*sizeof(float), cudaMemcpyDeviceToDevice, 0);
        dv_scatter_k<<<PE/128, 96>>>(v_in, v_out, idx_i, idx_j, cutoffs);
        // s += segment_sum(m)
        m_scatter_k<<<PE/128, 128>>>(out_s, idx_i, cutoffs);

        // node update (Wemb folded into U1)
        prep_u1split_k<<<(FD*FD+255)/256, 256>>>(upd_W1 + (size_t)b*2*FD*FD, Wemb);
        { dim3 g(1, MT);
          gemm_k<<<g,256>>>(out_s, FD, pBh, pBl, upd_b1 + b*FD, pt, FD, NA, FD, FD, 0, 0); }
        prep_u2split_k<<<(FD*FD+255)/256, 256>>>(upd_W2 + (size_t)b*FD*FD);
        { dim3 g(1, MT);
          gemm_k<<<g,256>>>(pt, FD, pBh, pBl, upd_b2 + b*FD, out_s, FD, NA, FD, FD, 0, 1); }
    }
    (void)in_sizes; (void)n_in; (void)out_size;
}

// round 6
// speedup vs baseline: 1.2210x; 1.2210x over previous
#include <cuda_runtime.h>
#include <cuda_bf16.h>
#include <math.h>

#define NA 20000
#define PE 320000
#define FD 128
#define RD 64
#define DH 256
#define DG 192
#define KA 160      // a_* columns
#define KW1 224     // rbf(64) + a(160)
#define YW 512
#define NOACT (1<<30)

// ---------------- scratch (device globals; no allocation allowed) ----------
__device__ float g_u [PE*3];
__device__ float g_GM[(size_t)PE*DG];   // [g0 0:32 | g1 32:64 | Mi 64:192]
__device__ float g_Y [(size_t)NA*YW];   // [Yi 0:256 | Yj 256:512]
__device__ float g_v0[NA*96];
__device__ float g_v1[NA*96];
__device__ float g_b1c[DH];
__device__ float g_tbuf[NA*FD];
__device__ __align__(16) unsigned short g_Xh[(size_t)PE*KA];
__device__ __align__(16) unsigned short g_Xl[(size_t)PE*KA];
__device__ __align__(16) unsigned short g_Rh[(size_t)PE*RD];
__device__ __align__(16) unsigned short g_Rl[(size_t)PE*RD];
__device__ __align__(16) unsigned short g_Hh[(size_t)PE*DH];
__device__ __align__(16) unsigned short g_Hl[(size_t)PE*DH];
__device__ __align__(16) unsigned short g_Bh[YW*FD > DH*KW1 ? YW*FD : DH*KW1];
__device__ __align__(16) unsigned short g_Bl[YW*FD > DH*KW1 ? YW*FD : DH*KW1];
__device__ __align__(16) unsigned short g_B2h[DG*FD];   // [eqW2 64 rows | invW2 128 rows]
__device__ __align__(16) unsigned short g_B2l[DG*FD];

__device__ __forceinline__ float silu_f(float x){ return x/(1.f+__expf(-x)); }

__device__ __forceinline__ void split1(float x, unsigned short &h, unsigned short &l){
    __nv_bfloat16 hb = __float2bfloat16(x);
    float r = x - __bfloat162float(hb);
    __nv_bfloat16 lb = __float2bfloat16(r);
    h = *reinterpret_cast<unsigned short*>(&hb);
    l = *reinterpret_cast<unsigned short*>(&lb);
}
__device__ __forceinline__ void split2(float x, float y, unsigned &h, unsigned &l){
    __nv_bfloat162 hb = __floats2bfloat162_rn(x, y);
    float rx = x - __bfloat162float(hb.x);
    float ry = y - __bfloat162float(hb.y);
    __nv_bfloat162 lb = __floats2bfloat162_rn(rx, ry);
    h = *reinterpret_cast<unsigned*>(&hb);
    l = *reinterpret_cast<unsigned*>(&lb);
}

__device__ __forceinline__ void mma_bf16(float* c, unsigned a0,unsigned a1,unsigned a2,unsigned a3,
                                         unsigned b0, unsigned b1){
    asm volatile("mma.sync.aligned.m16n8k16.row.col.f32.bf16.bf16.f32 "
        "{%0,%1,%2,%3}, {%4,%5,%6,%7}, {%8,%9}, {%0,%1,%2,%3};"
        : "+f"(c[0]), "+f"(c[1]), "+f"(c[2]), "+f"(c[3])
        : "r"(a0),"r"(a1),"r"(a2),"r"(a3),"r"(b0),"r"(b1));
}
__device__ __forceinline__ void ldsm_x4(unsigned &r0,unsigned &r1,unsigned &r2,unsigned &r3, const void* p){
    unsigned addr = (unsigned)__cvta_generic_to_shared(p);
    asm volatile("ldmatrix.sync.aligned.m8n8.x4.shared.b16 {%0,%1,%2,%3}, [%4];"
        : "=r"(r0),"=r"(r1),"=r"(r2),"=r"(r3) : "r"(addr));
}
__device__ __forceinline__ void cp16(unsigned sdst, const void* src, int sz){
    asm volatile("cp.async.cg.shared.global [%0], [%1], 16, %2;\n"
        :: "r"(sdst), "l"(src), "r"(sz));
}

// ---------------- small prep kernels ---------------------------------------
__global__ void prep_u_k(const float* __restrict__ vectors, const float* __restrict__ dist){
    int idx = blockIdx.x*blockDim.x + threadIdx.x;
    if(idx >= PE*3) return;
    g_u[idx] = vectors[idx] / (dist[idx/3] + 0.001f);
}

__global__ void rbf_split_k(const float* __restrict__ rbfs){
    size_t idx = (size_t)blockIdx.x*blockDim.x + threadIdx.x;
    if(idx >= (size_t)PE*RD) return;
    unsigned short h,l; split1(rbfs[idx],h,l);
    g_Rh[idx]=h; g_Rl[idx]=l;
}

// Wy (K=128 -> N=512): node-side weights [W1i_eff | W1j_eff] with Wrbf folded.
__global__ void prep_wy_k(int b, const float* __restrict__ Wrbf,
                          const float* __restrict__ eqW1,
                          const float* __restrict__ invW1all){
    int idx = blockIdx.x*blockDim.x + threadIdx.x;
    if(idx >= YW*FD) return;
    int c = idx / FD, r = idx % FD;
    int sj = c >> 8;
    int cpack = c & 255;
    bool inv = (cpack >= FD);
    int cc = cpack & (FD-1);
    const float* W1 = inv ? (invW1all + (size_t)b*448*FD) : eqW1;
    int base;
    if(sj == 0) base = (inv || b==1) ? 192 : 32;
    else        base = (inv || b==1) ? 320 : 160;
    float val = W1[(base + r)*FD + cc];
    int wr = (sj ? 192 : 64) + r;
    #pragma unroll 8
    for(int k=0;k<32;k++) val += Wrbf[wr*32+k]*W1[k*FD+cc];
    unsigned short h,l; split1(val,h,l);
    g_Bh[(size_t)c*FD + r] = h;
    g_Bl[(size_t)c*FD + r] = l;
}

// W1 edge part (KW x 256)
__global__ void prep_w1split_k(int b, int KW, const float* __restrict__ Wrbf,
                          const float* __restrict__ eqW1, const float* __restrict__ eqb1,
                          const float* __restrict__ invW1all, const float* __restrict__ invb1all){
    int idx = blockIdx.x*blockDim.x + threadIdx.x;
    if(idx >= KW*DH) return;
    int r = idx / DH, c = idx % DH;
    bool inv = (c >= FD);
    int cc = c & (FD-1);
    const float* W1 = inv ? (invW1all + (size_t)b*448*FD) : eqW1;
    float acc = 0.f;
    if(r < 64){
        #pragma unroll 8
        for(int k=0;k<32;k++) acc += Wrbf[r*32+k]*W1[k*FD+cc];
    } else {
        int ar = r-64;
        if(inv || b==1) acc = W1[(32+ar)*FD+cc];
    }
    unsigned short h,l; split1(acc,h,l);
    g_Bh[(size_t)c*KW + r] = h;
    g_Bl[(size_t)c*KW + r] = l;
    if(r==0) g_b1c[c] = inv ? invb1all[b*FD+cc] : eqb1[cc];
}

// stage2 weights: rows 0:64 eqW2 (K=128), rows 64:192 invW2 (K=128); n-major
__global__ void prep_w2_k(int b, const float* __restrict__ eqW2,
                          const float* __restrict__ invW2all){
    int idx = blockIdx.x*blockDim.x + threadIdx.x;
    if(idx >= DG*FD) return;
    int c = idx / FD, r = idx % FD;
    float val;
    if(c < 64) val = eqW2[r*64 + c];
    else       val = invW2all[(size_t)b*FD*FD + r*FD + (c-64)];
    unsigned short h,l; split1(val,h,l);
    g_B2h[(size_t)c*FD + r] = h;
    g_B2l[(size_t)c*FD + r] = l;
}

// W1u = U1_top + Wemb @ U1_bot (128x128)
__global__ void prep_u1split_k(const float* __restrict__ U1, const float* __restrict__ Wemb){
    int idx = blockIdx.x*blockDim.x + threadIdx.x;
    if(idx >= FD*FD) return;
    int c = idx / FD, r = idx % FD;
    float val = U1[r*FD + c];
    #pragma unroll 8
    for(int k=0;k<FD;k++) val += Wemb[r*FD + k] * U1[(FD+k)*FD + c];
    unsigned short h,l; split1(val,h,l);
    g_Bh[(size_t)c*FD + r] = h;
    g_Bl[(size_t)c*FD + r] = l;
}
__global__ void prep_u2split_k(const float* __restrict__ U2){
    int idx = blockIdx.x*blockDim.x + threadIdx.x;
    if(idx >= FD*FD) return;
    int c = idx / FD, r = idx % FD;
    unsigned short h,l; split1(U2[r*FD + c],h,l);
    g_Bh[(size_t)c*FD + r] = h;
    g_Bl[(size_t)c*FD + r] = l;
}

// Per-edge a_* row (block 1 only), written pre-split
__global__ void edge_x_k(const float* __restrict__ v_in,
                         const int* __restrict__ idx_i, const int* __restrict__ idx_j){
    int p = blockIdx.x*8 + threadIdx.y;
    int lane = threadIdx.x;
    int i = idx_i[p], j = idx_j[p];
    float u0 = g_u[p*3+0], u1 = g_u[p*3+1], u2 = g_u[p*3+2];
    const float* vi  = v_in + (size_t)i*96;
    const float* vjp = v_in + (size_t)j*96;
    float vi0=vi[lane],  vi1=vi[32+lane],  vi2=vi[64+lane];
    float vj0=vjp[lane], vj1=vjp[32+lane], vj2=vjp[64+lane];
    float a0 = u0*vi0 + u1*vi1 + u2*vi2;
    float a1 = u0*vj0 + u1*vj1 + u2*vj2;
    float a2 = vi0*vj0 + vi1*vj1 + vi2*vj2;
    float a3 = vi0*vi0 + vi1*vi1 + vi2*vi2;
    float a4 = vj0*vj0 + vj1*vj1 + vj2*vj2;
    size_t base = (size_t)p*KA;
    unsigned short h,l;
    split1(a0,h,l); g_Xh[base+     lane]=h; g_Xl[base+     lane]=l;
    split1(a1,h,l); g_Xh[base+ 32+lane]=h; g_Xl[base+ 32+lane]=l;
    split1(a2,h,l); g_Xh[base+ 64+lane]=h; g_Xl[base+ 64+lane]=l;
    split1(a3,h,l); g_Xh[base+ 96+lane]=h; g_Xl[base+ 96+lane]=l;
    split1(a4,h,l); g_Xh[base+128+lane]=h; g_Xl[base+128+lane]=l;
}

// ---------------- standalone bf16x3 GEMM (node-side, fp32 A) ---------------
__global__ __launch_bounds__(256) void gemm_k(
    const float* __restrict__ A1, int lda1,
    const unsigned short* __restrict__ Bh, const unsigned short* __restrict__ Bl,
    const float* __restrict__ bias,
    float* __restrict__ C, int ldc,
    int M, int N, int K, int act_start, int accum)
{
    __shared__ unsigned As[2][128][20];
    __shared__ unsigned Bs[2][128][20];
    const int tid = threadIdx.x;
    const int lane = tid & 31, w = tid >> 5;
    const int wm = (w >> 2) * 64, wn = (w & 3) * 32;
    const int g = lane >> 2, tig = lane & 3;
    const int bm = blockIdx.y * 128, bn = blockIdx.x * 128;

    const int ar = tid >> 1;
    const int ak = (tid & 1) * 8;
    const int kc = ak >> 1;
    const int arow = bm + ar;
    const bool aok = arow < M;
    const bool bok = (bn + ar) < N;
    const unsigned short* Bhp = Bh + (size_t)(bn+ar)*K + ak;
    const unsigned short* Blp = Bl + (size_t)(bn+ar)*K + ak;

    float acc[4][4][4];
    #pragma unroll
    for(int i=0;i<4;i++)
        #pragma unroll
        for(int j=0;j<4;j++)
            #pragma unroll
            for(int q=0;q<4;q++) acc[i][j][q]=0.f;

    float4 a0v, a1v; uint4 bhv, blv;
    {
        const float* ap = A1 + (size_t)arow*lda1 + ak;
        a0v = aok ? *(const float4*)(ap)   : make_float4(0,0,0,0);
        a1v = aok ? *(const float4*)(ap+4) : make_float4(0,0,0,0);
    }
    bhv = bok ? *(const uint4*)(Bhp) : make_uint4(0,0,0,0);
    blv = bok ? *(const uint4*)(Blp) : make_uint4(0,0,0,0);

    const int nstage = K >> 4;
    for(int t=0; t<nstage; t++){
        const int cur = t & 1;
        {
            unsigned h0,l0,h1,l1,h2,l2,h3,l3;
            split2(a0v.x,a0v.y,h0,l0); split2(a0v.z,a0v.w,h1,l1);
            split2(a1v.x,a1v.y,h2,l2); split2(a1v.z,a1v.w,h3,l3);
            *(uint4*)&As[cur][ar][kc]   = make_uint4(h0,h1,h2,h3);
            *(uint4*)&As[cur][ar][8+kc] = make_uint4(l0,l1,l2,l3);
            *(uint4*)&Bs[cur][ar][kc]   = bhv;
            *(uint4*)&Bs[cur][ar][8+kc] = blv;
        }
        __syncthreads();
        if(t+1 < nstage){
            const int kk = (t+1)*16 + ak;
            const float* ap = A1 + (size_t)arow*lda1 + kk;
            a0v = aok ? *(const float4*)(ap)   : make_float4(0,0,0,0);
            a1v = aok ? *(const float4*)(ap+4) : make_float4(0,0,0,0);
            bhv = bok ? *(const uint4*)(Bhp + (t+1)*16) : make_uint4(0,0,0,0);
            blv = bok ? *(const uint4*)(Blp + (t+1)*16) : make_uint4(0,0,0,0);
        }
        unsigned bf[4][4];
        #pragma unroll
        for(int nt=0;nt<4;nt++){
            const unsigned* bp = &Bs[cur][wn + nt*8 + g][0];
            bf[nt][0]=bp[tig];   bf[nt][1]=bp[tig+4];
            bf[nt][2]=bp[8+tig]; bf[nt][3]=bp[8+tig+4];
        }
        #pragma unroll
        for(int mt=0;mt<4;mt++){
            unsigned ah0,ah1,ah2,ah3, al0,al1,al2,al3;
            const int row = wm + mt*16 + (lane & 15);
            const int kq  = (lane >> 4) * 4;
            ldsm_x4(ah0,ah1,ah2,ah3, &As[cur][row][kq]);
            ldsm_x4(al0,al1,al2,al3, &As[cur][row][8+kq]);
            #pragma unroll
            for(int nt=0;nt<4;nt++){
                mma_bf16(acc[mt][nt], ah0,ah1,ah2,ah3, bf[nt][0], bf[nt][1]);
                mma_bf16(acc[mt][nt], al0,al1,al2,al3, bf[nt][0], bf[nt][1]);
                mma_bf16(acc[mt][nt], ah0,ah1,ah2,ah3, bf[nt][2], bf[nt][3]);
            }
        }
        __syncthreads();
    }

    #pragma unroll
    for(int mt=0;mt<4;mt++){
        const int r0 = bm + wm + mt*16 + g;
        const bool r0ok = r0 < M, r1ok = (r0+8) < M;
        #pragma unroll
        for(int nt=0;nt<4;nt++){
            const int c0 = bn + wn + nt*8 + 2*tig;
            if(c0 >= N) continue;
            float x0=acc[mt][nt][0], x1=acc[mt][nt][1], x2=acc[mt][nt][2], x3=acc[mt][nt][3];
            if(c0 >= act_start){
                float bb0 = bias[c0], bb1 = bias[c0+1];
                x0 = silu_f(x0+bb0); x1 = silu_f(x1+bb1);
                x2 = silu_f(x2+bb0); x3 = silu_f(x3+bb1);
            }
            if(r0ok){
                float2* o = (float2*)&C[(size_t)r0*ldc + c0];
                if(accum){ float2 p=*o; *o = make_float2(p.x+x0, p.y+x1); }
                else      *o = make_float2(x0, x1);
            }
            if(r1ok){
                float2* o = (float2*)&C[(size_t)(r0+8)*ldc + c0];
                if(accum){ float2 p=*o; *o = make_float2(p.x+x2, p.y+x3); }
                else      *o = make_float2(x2, x3);
            }
        }
    }
}

// ---------------- edge bf16x3 GEMM: pre-split A, cp.async pipeline ---------
// A = [A1h/A1l (K1 cols, lda1) | A2h/A2l (lda2)], bf16 split, row-major.
// M must be a multiple of 128 (full tiles). N guard on B rows via zfill.
// If Hh != null: epilogue writes silu(acc + bias + Yi + Yj) as split bf16 to Hh/Hl.
// Else: writes fp32 to C (+coff), silu+bias for cols >= act_start.
#define NBUF 4
#define AS_OFF(b,r,c) ((b)*2560 + (r)*20 + (c))
#define BS_OFF(b,r,c) (10240 + (b)*2560 + (r)*20 + (c))
#define EDGE_SMEM (20480*4)

__global__ __launch_bounds__(256,2) void gemm_bf_k(
    const unsigned short* __restrict__ A1h, const unsigned short* __restrict__ A1l,
    int lda1, int K1,
    const unsigned short* __restrict__ A2h, const unsigned short* __restrict__ A2l,
    int lda2,
    const unsigned short* __restrict__ Bh, const unsigned short* __restrict__ Bl,
    const float* __restrict__ bias,
    const float* __restrict__ Yg, const int* __restrict__ gi, const int* __restrict__ gj,
    unsigned short* __restrict__ Hh, unsigned short* __restrict__ Hl, int ldh,
    float* __restrict__ C, int ldc, int coff,
    int N, int K, int act_start)
{
    extern __shared__ unsigned sm[];
    const unsigned smb = (unsigned)__cvta_generic_to_shared(sm);
    const int tid = threadIdx.x;
    const int lane = tid & 31, w = tid >> 5;
    const int wm = (w >> 2) * 64, wn = (w & 3) * 32;
    const int g = lane >> 2, tig = lane & 3;
    const int bm = blockIdx.y * 128, bn = blockIdx.x * 128;

    const int ar = tid >> 1;
    const int koff = (tid & 1) * 8;
    const int kc = koff >> 1;
    const int arow = bm + ar;
    const int brow = bn + ar;
    const int bsz = (brow < N) ? 16 : 0;
    const int nstage = K >> 4;

    // ---- async loader ----
    auto issue = [&](int stage){
        const int buf = stage & (NBUF-1);
        const int kk = stage*16 + koff;
        const unsigned short *ah, *al;
        if(kk < K1){ ah = A1h + (size_t)arow*lda1 + kk; al = A1l + (size_t)arow*lda1 + kk; }
        else       { ah = A2h + (size_t)arow*lda2 + (kk-K1); al = A2l + (size_t)arow*lda2 + (kk-K1); }
        cp16(smb + 4*AS_OFF(buf,ar,kc),   ah, 16);
        cp16(smb + 4*AS_OFF(buf,ar,8+kc), al, 16);
        cp16(smb + 4*BS_OFF(buf,ar,kc),   Bh + (size_t)brow*K + kk, bsz);
        cp16(smb + 4*BS_OFF(buf,ar,8+kc), Bl + (size_t)brow*K + kk, bsz);
        asm volatile("cp.async.commit_group;\n");
    };

    float acc[4][4][4];
    #pragma unroll
    for(int i=0;i<4;i++)
        #pragma unroll
        for(int j=0;j<4;j++)
            #pragma unroll
            for(int q=0;q<4;q++) acc[i][j][q]=0.f;

    issue(0); issue(1); issue(2);

    for(int t=0; t<nstage; t++){
        if(t+2 < nstage)       asm volatile("cp.async.wait_group 2;\n");
        else if(t+1 < nstage)  asm volatile("cp.async.wait_group 1;\n");
        else                   asm volatile("cp.async.wait_group 0;\n");
        __syncthreads();
        if(t+3 < nstage) issue(t+3);

        const int buf = t & (NBUF-1);
        unsigned bf[4][4];
        #pragma unroll
        for(int nt=0;nt<4;nt++){
            const unsigned* bp = &sm[BS_OFF(buf, wn + nt*8 + g, 0)];
            bf[nt][0]=bp[tig];   bf[nt][1]=bp[tig+4];
            bf[nt][2]=bp[8+tig]; bf[nt][3]=bp[8+tig+4];
        }
        #pragma unroll
        for(int mt=0;mt<4;mt++){
            unsigned ah0,ah1,ah2,ah3, al0,al1,al2,al3;
            const int row = wm + mt*16 + (lane & 15);
            const int kq  = (lane >> 4) * 4;
            ldsm_x4(ah0,ah1,ah2,ah3, &sm[AS_OFF(buf,row,kq)]);
            ldsm_x4(al0,al1,al2,al3, &sm[AS_OFF(buf,row,8+kq)]);
            #pragma unroll
            for(int nt=0;nt<4;nt++){
                mma_bf16(acc[mt][nt], ah0,ah1,ah2,ah3, bf[nt][0], bf[nt][1]);
                mma_bf16(acc[mt][nt], al0,al1,al2,al3, bf[nt][0], bf[nt][1]);
                mma_bf16(acc[mt][nt], ah0,ah1,ah2,ah3, bf[nt][2], bf[nt][3]);
            }
        }
    }

    if(Hh){
        // stage1 epilogue: bias + Y gather + silu -> split bf16 H
        #pragma unroll
        for(int mt=0;mt<4;mt++){
            const int r0 = bm + wm + mt*16 + g;
            const int i0=gi[r0],   j0=gj[r0];
            const int i1=gi[r0+8], j1=gj[r0+8];
            #pragma unroll
            for(int nt=0;nt<4;nt++){
                const int c0g = bn + wn + nt*8 + 2*tig;
                float x0=acc[mt][nt][0], x1=acc[mt][nt][1], x2=acc[mt][nt][2], x3=acc[mt][nt][3];
                float2 yi = *(const float2*)&Yg[(size_t)i0*YW + c0g];
                float2 yj = *(const float2*)&Yg[(size_t)j0*YW + 256 + c0g];
                x0 += yi.x + yj.x; x1 += yi.y + yj.y;
                float2 yi1 = *(const float2*)&Yg[(size_t)i1*YW + c0g];
                float2 yj1 = *(const float2*)&Yg[(size_t)j1*YW + 256 + c0g];
                x2 += yi1.x + yj1.x; x3 += yi1.y + yj1.y;
                float bb0 = bias[c0g], bb1 = bias[c0g+1];
                x0 = silu_f(x0+bb0); x1 = silu_f(x1+bb1);
                x2 = silu_f(x2+bb0); x3 = silu_f(x3+bb1);
                unsigned h,l;
                split2(x0,x1,h,l);
                *(unsigned*)&Hh[(size_t)r0*ldh + c0g] = h;
                *(unsigned*)&Hl[(size_t)r0*ldh + c0g] = l;
                split2(x2,x3,h,l);
                *(unsigned*)&Hh[(size_t)(r0+8)*ldh + c0g] = h;
                *(unsigned*)&Hl[(size_t)(r0+8)*ldh + c0g] = l;
            }
        }
    } else {
        #pragma unroll
        for(int mt=0;mt<4;mt++){
            const int r0 = bm + wm + mt*16 + g;
            #pragma unroll
            for(int nt=0;nt<4;nt++){
                const int c0 = bn + wn + nt*8 + 2*tig;
                if(c0 >= N) continue;
                float x0=acc[mt][nt][0], x1=acc[mt][nt][1], x2=acc[mt][nt][2], x3=acc[mt][nt][3];
                if(c0 >= act_start){
                    float bb0 = bias[c0], bb1 = bias[c0+1];
                    x0 = silu_f(x0+bb0); x1 = silu_f(x1+bb1);
                    x2 = silu_f(x2+bb0); x3 = silu_f(x3+bb1);
                }
                *(float2*)&C[(size_t)r0*ldc + coff + c0]     = make_float2(x0,x1);
                *(float2*)&C[(size_t)(r0+8)*ldc + coff + c0] = make_float2(x2,x3);
            }
        }
    }
}

// ---------------- segment-sum scatters (idx_i sorted) -----------------------
__global__ void m_scatter_k(float* __restrict__ s_out,
                            const int* __restrict__ idx_i,
                            const float* __restrict__ cutoffs){
    int f  = threadIdx.x;
    int p0 = blockIdx.x*128;
    float acc = 0.f; int cur = idx_i[p0];
    for(int e=0;e<128;e++){
        int p = p0+e;
        int ii = idx_i[p];
        if(ii != cur){ atomicAdd(&s_out[(size_t)cur*FD+f], acc); acc = 0.f; cur = ii; }
        acc += g_GM[(size_t)p*DG + 64 + f] * cutoffs[p];
    }
    atomicAdd(&s_out[(size_t)cur*FD+f], acc);
}

__global__ void dv_scatter_k(const float* __restrict__ v_in, float* __restrict__ v_out,
                             const int* __restrict__ idx_i, const int* __restrict__ idx_j,
                             const float* __restrict__ cutoffs){
    int t = threadIdx.x;
    int m = t & 31, d = t >> 5;
    int p0 = blockIdx.x*128;
    float acc = 0.f; int cur = idx_i[p0];
    for(int e=0;e<128;e++){
        int p = p0+e;
        int ii = idx_i[p];
        if(ii != cur){ atomicAdd(&v_out[(size_t)cur*96+t], acc); acc = 0.f; cur = ii; }
        int j = idx_j[p];
        float g0 = g_GM[(size_t)p*DG + m];
        float g1 = g_GM[(size_t)p*DG + 32 + m];
        float vj = v_in[(size_t)j*96 + t];
        acc += (g0*g_u[p*3+d] + g1*vj) * cutoffs[p];
    }
    atomicAdd(&v_out[(size_t)cur*96+t], acc);
}

// ---------------- launch ----------------------------------------------------
extern "C" void kernel_launch(void* const* d_in, const int* in_sizes, int n_in,
                              void* d_out, int out_size)
{
    const float* features = (const float*)d_in[0];
    const float* distances= (const float*)d_in[1];
    const float* vectors  = (const float*)d_in[2];
    const float* cutoffs  = (const float*)d_in[3];
    const float* rbfs     = (const float*)d_in[4];
    const int*   idx_i    = (const int*)  d_in[5];
    const int*   idx_j    = (const int*)  d_in[6];
    const float* Wrbf     = (const float*)d_in[7];
    const float* Wemb     = (const float*)d_in[8];
    const float* eq0_W1   = (const float*)d_in[9];
    const float* eq0_b1   = (const float*)d_in[10];
    const float* eq0_W2   = (const float*)d_in[11];
    const float* eq1_W1   = (const float*)d_in[12];
    const float* eq1_b1   = (const float*)d_in[13];
    const float* eq1_W2   = (const float*)d_in[14];
    const float* inv_W1   = (const float*)d_in[15];
    const float* inv_b1   = (const float*)d_in[16];
    const float* inv_W2   = (const float*)d_in[17];
    const float* inv_b2   = (const float*)d_in[18];
    const float* upd_W1   = (const float*)d_in[19];
    const float* upd_b1   = (const float*)d_in[20];
    const float* upd_W2   = (const float*)d_in[21];
    const float* upd_b2   = (const float*)d_in[22];

    float* out_s = (float*)d_out;
    float* out_v = out_s + (size_t)NA*FD;

    float *pGM,*pY,*pv0,*pv1,*pb1,*pt;
    unsigned short *pBh,*pBl,*pB2h,*pB2l,*pXh,*pXl,*pRh,*pRl,*pHh,*pHl;
    cudaGetSymbolAddress((void**)&pGM, g_GM);
    cudaGetSymbolAddress((void**)&pY,  g_Y);
    cudaGetSymbolAddress((void**)&pv0, g_v0);
    cudaGetSymbolAddress((void**)&pv1, g_v1);
    cudaGetSymbolAddress((void**)&pb1, g_b1c);
    cudaGetSymbolAddress((void**)&pt,  g_tbuf);
    cudaGetSymbolAddress((void**)&pBh, g_Bh);
    cudaGetSymbolAddress((void**)&pBl, g_Bl);
    cudaGetSymbolAddress((void**)&pB2h, g_B2h);
    cudaGetSymbolAddress((void**)&pB2l, g_B2l);
    cudaGetSymbolAddress((void**)&pXh, g_Xh);
    cudaGetSymbolAddress((void**)&pXl, g_Xl);
    cudaGetSymbolAddress((void**)&pRh, g_Rh);
    cudaGetSymbolAddress((void**)&pRl, g_Rl);
    cudaGetSymbolAddress((void**)&pHh, g_Hh);
    cudaGetSymbolAddress((void**)&pHl, g_Hl);

    cudaFuncSetAttribute(gemm_bf_k, cudaFuncAttributeMaxDynamicSharedMemorySize, EDGE_SMEM);

    cudaMemcpyAsync(out_s, features, (size_t)NA*FD*sizeof(float), cudaMemcpyDeviceToDevice, 0);
    cudaMemsetAsync(pv0, 0, (size_t)NA*96*sizeof(float), 0);
    prep_u_k<<<(PE*3+255)/256, 256>>>(vectors, distances);
    rbf_split_k<<<(int)(((size_t)PE*RD+255)/256), 256>>>(rbfs);

    const int MT = (NA+127)/128;

    for(int b=0;b<2;b++){
        const float* eqW1 = b ? eq1_W1 : eq0_W1;
        const float* eqb1 = b ? eq1_b1 : eq0_b1;
        const float* eqW2 = b ? eq1_W2 : eq0_W2;
        float* v_in  = b ? pv1  : pv0;
        float* v_out = b ? out_v: pv1;
        const int KW = b ? KW1 : 64;

        // Y = s @ [W1i_eff | W1j_eff]   (NA,128)@(128,512)
        prep_wy_k<<<(YW*FD+255)/256, 256>>>(b, Wrbf, eqW1, inv_W1);
        { dim3 g(4, MT);
          gemm_k<<<g,256>>>(out_s, FD, pBh, pBl, nullptr, pY, YW, NA, YW, FD, NOACT, 0); }

        prep_w1split_k<<<(KW*DH+255)/256, 256>>>(b, KW, Wrbf, eqW1, eqb1, inv_W1, inv_b1);
        prep_w2_k<<<(DG*FD+255)/256, 256>>>(b, eqW2, inv_W2);
        if(b) edge_x_k<<<PE/8, dim3(32,8)>>>(v_in, idx_i, idx_j);

        // GEMM1: H(split) = silu(rbf@W1r [+ a@W1a] + Y_i + Y_j + b1)
        { dim3 g(2, PE/128);
          gemm_bf_k<<<g,256,EDGE_SMEM>>>(pRh, pRl, RD, RD, pXh, pXl, KA,
                                         pBh, pBl, pb1,
                                         pY, idx_i, idx_j,
                                         pHh, pHl, DH,
                                         nullptr, 0, 0, DH, KW, 0); }

        // GEMM2-G: G = H_eq @ eqW2   (raw, N=64)
        { dim3 g(1, PE/128);
          gemm_bf_k<<<g,256,EDGE_SMEM>>>(pHh, pHl, DH, 0, pHh, pHl, DH,
                                         pB2h, pB2l, nullptr,
                                         nullptr, nullptr, nullptr,
                                         nullptr, nullptr, 0,
                                         pGM, DG, 0, 64, FD, NOACT); }
        // GEMM2-Mi: Mi = silu(H_inv @ invW2 + invb2)   (N=128)
        { dim3 g(1, PE/128);
          gemm_bf_k<<<g,256,EDGE_SMEM>>>(pHh+FD, pHl+FD, DH, 0, pHh+FD, pHl+FD, DH,
                                         pB2h + (size_t)64*FD, pB2l + (size_t)64*FD, inv_b2 + b*FD,
                                         nullptr, nullptr, nullptr,
                                         nullptr, nullptr, 0,
                                         pGM, DG, 64, FD, FD, 0); }

        // v_out = v_in + segment_sum(dv)
        cudaMemcpyAsync(v_out, v_in, (size_t)NA*96*sizeof(float), cudaMemcpyDeviceToDevice, 0);
        dv_scatter_k<<<PE/128, 96>>>(v_in, v_out, idx_i, idx_j, cutoffs);
        // s += segment_sum(m)
        m_scatter_k<<<PE/128, 128>>>(out_s, idx_i, cutoffs);

        // node update (Wemb folded into U1)
        prep_u1split_k<<<(FD*FD+255)/256, 256>>>(upd_W1 + (size_t)b*2*FD*FD, Wemb);
        { dim3 g(1, MT);
          gemm_k<<<g,256>>>(out_s, FD, pBh, pBl, upd_b1 + b*FD, pt, FD, NA, FD, FD, 0, 0); }
        prep_u2split_k<<<(FD*FD+255)/256, 256>>>(upd_W2 + (size_t)b*FD*FD);
        { dim3 g(1, MT);
          gemm_k<<<g,256>>>(pt, FD, pBh, pBl, upd_b2 + b*FD, out_s, FD, NA, FD, FD, 0, 1); }
    }
    (void)in_sizes; (void)n_in; (void)out_size;
}